// round 15
// baseline (speedup 1.0000x reference)
#include <cuda_runtime.h>
#include <cuda_fp16.h>
#include <math.h>
#include <stdint.h>

#define TT   4096
#define DM   1024
#define HH   4096
#define NE   8
#define NSEG 9
#define CAP  4096

// smem: per stage A(128x144B) + B(128x144B); 3 stages; 2 CTAs/SM
#define A_TILE_B 18432
#define B_TILE_B 18432
#define STAGE_B  36864
#define SMEM_SZ  110592

// aux kernel ranges: wcvt W1 + gate
#define W1_BLKS    36864
#define GATE_BLKS  512
// gemm1 fused grid: gemm tiles + wcvt W2 + zero(out)
#define G1_TILES   9216          // 32 x 32 x 9
#define W2_BLKS    36864
#define ZERO_BLKS  4096

// ---------------- scratch (__device__ globals; allocation-free rule) -------
__device__ int   g_cnt[NSEG];
__device__ int   g_rowmap[NE * CAP];
__device__ float g_sgate[NE * CAP];

__device__ __align__(16) __half g_x [(size_t)NSEG * CAP * DM];
__device__ __align__(16) __half g_w1[(size_t)NSEG * HH * DM];
__device__ __align__(16) __half g_w2[(size_t)NSEG * DM * HH];
__device__ __align__(16) __half g_h [(size_t)NSEG * CAP * HH];

// ---------------- helpers ---------------------------------------------------
__device__ __forceinline__ uint32_t s2u(const void* p) {
    uint32_t a;
    asm("{ .reg .u64 t; cvta.to.shared.u64 t, %1; cvt.u32.u64 %0, t; }" : "=r"(a) : "l"(p));
    return a;
}
__device__ __forceinline__ void cpasync16(uint32_t dst, const void* src) {
    asm volatile("cp.async.cg.shared.global [%0], [%1], 16;" :: "r"(dst), "l"(src) : "memory");
}
__device__ __forceinline__ void cp_commit() { asm volatile("cp.async.commit_group;" ::: "memory"); }
template <int N> __device__ __forceinline__ void cp_wait() {
    asm volatile("cp.async.wait_group %0;" :: "n"(N) : "memory");
}
__device__ __forceinline__ void ldsm4(uint32_t* r, uint32_t a) {
    asm volatile("ldmatrix.sync.aligned.m8n8.x4.shared.b16 {%0,%1,%2,%3}, [%4];"
                 : "=r"(r[0]), "=r"(r[1]), "=r"(r[2]), "=r"(r[3]) : "r"(a));
}
__device__ __forceinline__ void ldsm2(uint32_t* r, uint32_t a) {
    asm volatile("ldmatrix.sync.aligned.m8n8.x2.shared.b16 {%0,%1}, [%2];"
                 : "=r"(r[0]), "=r"(r[1]) : "r"(a));
}
__device__ __forceinline__ void mma16816(float* c, const uint32_t* a, const uint32_t* b) {
    asm volatile("mma.sync.aligned.m16n8k16.row.col.f32.f16.f16.f32 "
                 "{%0,%1,%2,%3}, {%4,%5,%6,%7}, {%8,%9}, {%0,%1,%2,%3};"
                 : "+f"(c[0]), "+f"(c[1]), "+f"(c[2]), "+f"(c[3])
                 : "r"(a[0]), "r"(a[1]), "r"(a[2]), "r"(a[3]), "r"(b[0]), "r"(b[1]));
}
// silu via hardware tanh: x * (0.5 + 0.5*tanh(x/2)) — 1 MUFU instead of 2
__device__ __forceinline__ float silu_f(float v) {
    float t;
    asm("tanh.approx.f32 %0, %1;" : "=f"(t) : "f"(0.5f * v));
    return v * fmaf(0.5f, t, 0.5f);
}
// fp32 -> fp16 convert of 1024 float4 per block (256 thr x 1 float4)
__device__ __forceinline__ void wcvt_blk(const float* __restrict__ src,
                                         __half* __restrict__ dst, int blk) {
    size_t i4 = (size_t)blk * 256 + threadIdx.x;
    float4 v = ((const float4*)src)[i4];
    __half2* p = (__half2*)(dst + i4 * 4);
    p[0] = __floats2half2_rn(v.x, v.y);
    p[1] = __floats2half2_rn(v.z, v.w);
}

// ---------------- reset ------------------------------------------------------
__global__ void reset_k() {
    int i = threadIdx.x;
    if (i < NE) g_cnt[i] = 0;
    if (i == NE) g_cnt[NE] = TT;
}

// ---------------- aux: wcvt W1 | gate ----------------------------------------
__global__ void aux_k(const float* __restrict__ x,  const float* __restrict__ gw,
                      const float* __restrict__ sw1, const float* __restrict__ ew1) {
    int bid = blockIdx.x;
    if (bid < W1_BLKS) {
        int seg = bid / 4096, blk = bid % 4096;
        size_t segoff = (size_t)seg * HH * DM;
        wcvt_blk((seg == NE) ? sw1 : (ew1 + segoff), g_w1 + segoff, blk);
        return;
    }
    bid -= W1_BLKS;
    {
        // ---- gating: one warp per token ----
        int gtid = bid * 256 + threadIdx.x;
        int t = gtid >> 5, lane = gtid & 31;
        const float* xr = x + (size_t)t * DM;
        float acc[NE];
#pragma unroll
        for (int e = 0; e < NE; e++) acc[e] = 0.f;
        for (int k = lane; k < DM; k += 32) {
            float xv = xr[k];
#pragma unroll
            for (int e = 0; e < NE; e++) acc[e] += xv * gw[e * DM + k];
        }
#pragma unroll
        for (int e = 0; e < NE; e++) {
#pragma unroll
            for (int o = 16; o > 0; o >>= 1) acc[e] += __shfl_xor_sync(0xffffffffu, acc[e], o);
        }
        if (lane == 0) {
            int i0 = 0; float v0 = acc[0];
#pragma unroll
            for (int e = 1; e < NE; e++) if (acc[e] > v0) { v0 = acc[e]; i0 = e; }
            int i1 = -1; float v1 = -1e30f;
#pragma unroll
            for (int e = 0; e < NE; e++) if (e != i0 && acc[e] > v1) { v1 = acc[e]; i1 = e; }
            float ex = expf(v1 - v0);
            float g0 = 1.f / (1.f + ex);
            float g1 = ex / (1.f + ex);
            int p0 = atomicAdd(&g_cnt[i0], 1);
            g_rowmap[i0 * CAP + p0] = t; g_sgate[i0 * CAP + p0] = g0;
            int p1 = atomicAdd(&g_cnt[i1], 1);
            g_rowmap[i1 * CAP + p1] = t; g_sgate[i1 * CAP + p1] = g1;
        }
    }
}

// ---------------- gather + convert activations per segment -------------------
__global__ void gather_k(const float* __restrict__ x) {
    int seg = blockIdx.y, slot = blockIdx.x;
    int cnt = g_cnt[seg];
    int pad = (cnt + 127) & ~127;
    if (slot >= pad) return;
    size_t drow = ((size_t)seg * CAP + slot) * DM;
    int i = threadIdx.x;
    float4 v = make_float4(0.f, 0.f, 0.f, 0.f);
    if (slot < cnt) {
        int tok = (seg == NE) ? slot : g_rowmap[seg * CAP + slot];
        v = ((const float4*)(x + (size_t)tok * DM))[i];
    }
    __half2* p = (__half2*)(g_x + drow + (size_t)i * 4);
    p[0] = __floats2half2_rn(v.x, v.y);
    p[1] = __floats2half2_rn(v.z, v.w);
}

// ---------------- GEMM core (verified R14 inner loop) ------------------------
// 128x128 CTA tile, 8 warps 64x32, 3-stage cp.async, occ 2
template <int PHASE>
__device__ __forceinline__ void gemm_body(float* __restrict__ out,
                                          int bx, int by, int seg) {
    constexpr int KLEN = (PHASE == 1) ? DM : HH;
    constexpr int NDIM = (PHASE == 1) ? HH : DM;
    constexpr int NC   = KLEN / 64;

    const int cnt = g_cnt[seg];
    const int m0  = by * 128;
    if (m0 >= cnt) return;
    const int n0  = bx * 128;

    extern __shared__ char smem[];
    const uint32_t sb = s2u(smem);

    const int tid  = threadIdx.x;
    const int lane = tid & 31;
    const int warp = tid >> 5;
    const int wm   = (warp & 1) * 64;
    const int wn   = (warp >> 1) * 32;

    const __half* Asrc, * Bsrc;
    if (PHASE == 1) {
        Asrc = g_x  + ((size_t)seg * CAP  + m0) * KLEN;
        Bsrc = g_w1 + ((size_t)seg * NDIM + n0) * KLEN;
    } else {
        Asrc = g_h  + ((size_t)seg * CAP  + m0) * KLEN;
        Bsrc = g_w2 + ((size_t)seg * NDIM + n0) * KLEN;
    }

    auto issue = [&](int c) {
        uint32_t base = sb + (c % 3) * STAGE_B;
#pragma unroll
        for (int it = 0; it < 4; it++) {
            int o = tid + it * 256;
            int row = o >> 3, q = o & 7;
            cpasync16(base + row * 144 + q * 16,
                      Asrc + (size_t)row * KLEN + c * 64 + q * 8);
        }
#pragma unroll
        for (int it = 0; it < 4; it++) {
            int o = tid + it * 256;
            int row = o >> 3, q = o & 7;
            cpasync16(base + A_TILE_B + row * 144 + q * 16,
                      Bsrc + (size_t)row * KLEN + c * 64 + q * 8);
        }
        cp_commit();
    };

    float acc[4][4][4];
#pragma unroll
    for (int mi = 0; mi < 4; mi++)
#pragma unroll
        for (int ni = 0; ni < 4; ni++)
#pragma unroll
            for (int r = 0; r < 4; r++) acc[mi][ni][r] = 0.f;

    issue(0);
    issue(1);

    for (int c = 0; c < NC; c++) {
        if (c + 1 < NC) cp_wait<1>();
        else            cp_wait<0>();
        __syncthreads();
        if (c + 2 < NC) issue(c + 2);

        uint32_t Ab = sb + (c % 3) * STAGE_B;
        uint32_t Bb = Ab + A_TILE_B;

#pragma unroll
        for (int ks = 0; ks < 4; ks++) {
            const uint32_t acol = ks * 32 + (lane >> 4) * 16;
            const uint32_t bcol = ks * 32 + ((lane >> 3) & 1) * 16;
            uint32_t ah[4][4], bh[4][2];
#pragma unroll
            for (int mi = 0; mi < 4; mi++)
                ldsm4(ah[mi], Ab + (wm + mi * 16 + (lane & 15)) * 144 + acol);
#pragma unroll
            for (int ni = 0; ni < 4; ni++)
                ldsm2(bh[ni], Bb + (wn + ni * 8 + (lane & 7)) * 144 + bcol);
#pragma unroll
            for (int mi = 0; mi < 4; mi++)
#pragma unroll
                for (int ni = 0; ni < 4; ni++) mma16816(acc[mi][ni], ah[mi], bh[ni]);
        }
    }
    __syncthreads();

    // ---- epilogue: regs -> smem (f32, stride 132) -> gmem ----
    float* SF = (float*)smem;
    int*   RI = (int*)(smem + 128 * 132 * 4);
    float* GV = (float*)(smem + 128 * 132 * 4 + 512);

#pragma unroll
    for (int mi = 0; mi < 4; mi++)
#pragma unroll
        for (int ni = 0; ni < 4; ni++)
#pragma unroll
            for (int r = 0; r < 4; r++) {
                int row = wm + mi * 16 + (lane >> 2) + (r >> 1) * 8;
                int col = wn + ni * 8 + (lane & 3) * 2 + (r & 1);
                float v = acc[mi][ni][r];
                if (PHASE == 1) v = silu_f(v);
                SF[row * 132 + col] = v;
            }
    if (PHASE == 2 && tid < 128) {
        int m = m0 + tid;
        if (seg == NE)      { RI[tid] = m; GV[tid] = 1.f; }
        else if (m < cnt)   { RI[tid] = g_rowmap[seg * CAP + m]; GV[tid] = g_sgate[seg * CAP + m]; }
        else                { RI[tid] = 0; GV[tid] = 0.f; }
    }
    __syncthreads();

    if (PHASE == 1) {
        for (int i = tid; i < 128 * 32; i += 256) {
            int r = i >> 5, q = i & 31;
            float4 v = *(const float4*)(SF + r * 132 + q * 4);
            size_t drow = (size_t)seg * CAP + m0 + r;
            __half2* p = (__half2*)(g_h + drow * HH + n0 + q * 4);
            p[0] = __floats2half2_rn(v.x, v.y);
            p[1] = __floats2half2_rn(v.z, v.w);
        }
    } else {
        for (int i = tid; i < 128 * 32; i += 256) {
            int r = i >> 5, q = i & 31;
            float4 v = *(const float4*)(SF + r * 132 + q * 4);
            float gv = GV[r];
            float* op = out + (size_t)RI[r] * DM + n0 + q * 4;
            atomicAdd(op + 0, gv * v.x);
            atomicAdd(op + 1, gv * v.y);
            atomicAdd(op + 2, gv * v.z);
            atomicAdd(op + 3, gv * v.w);
        }
    }
}

// ---------------- gemm1 fused: gemm tiles + wcvt W2 + zero(out) --------------
__global__ __launch_bounds__(256, 2) void gemm1f_k(float* __restrict__ out,
                                                   const float* __restrict__ sw2,
                                                   const float* __restrict__ ew2) {
    int bid = blockIdx.x;
    if (bid >= G1_TILES) {
        bid -= G1_TILES;
        if (bid < W2_BLKS) {
            int seg = bid / 4096, blk = bid % 4096;
            size_t segoff = (size_t)seg * HH * DM;
            wcvt_blk((seg == NE) ? sw2 : (ew2 + segoff), g_w2 + segoff, blk);
        } else {
            size_t i = (size_t)(bid - W2_BLKS) * 256 + threadIdx.x;
            ((float4*)out)[i] = make_float4(0.f, 0.f, 0.f, 0.f);
        }
        return;
    }
    int bx = bid & 31;           // HH/128 = 32
    int by = (bid >> 5) & 31;    // CAP/128 = 32
    int seg = bid >> 10;         // 9 segments
    gemm_body<1>(out, bx, by, seg);
}

// ---------------- gemm2 ------------------------------------------------------
__global__ __launch_bounds__(256, 2) void gemm2_k(float* __restrict__ out) {
    gemm_body<2>(out, blockIdx.x, blockIdx.y, blockIdx.z);
}

// ---------------------------------------------------------------------------
extern "C" void kernel_launch(void* const* d_in, const int* in_sizes, int n_in,
                              void* d_out, int out_size) {
    const float* x   = (const float*)d_in[0];
    const float* sw1 = (const float*)d_in[1];
    const float* sw2 = (const float*)d_in[2];
    const float* ew1 = (const float*)d_in[3];
    const float* ew2 = (const float*)d_in[4];
    const float* gw  = (const float*)d_in[5];
    float* out = (float*)d_out;

    cudaFuncSetAttribute(gemm1f_k, cudaFuncAttributeMaxDynamicSharedMemorySize, SMEM_SZ);
    cudaFuncSetAttribute(gemm2_k,  cudaFuncAttributeMaxDynamicSharedMemorySize, SMEM_SZ);

    reset_k<<<1, 32>>>();
    aux_k<<<W1_BLKS + GATE_BLKS, 256>>>(x, gw, sw1, ew1);
    gather_k<<<dim3(CAP, NSEG), 256>>>(x);
    gemm1f_k<<<G1_TILES + W2_BLKS + ZERO_BLKS, 256, SMEM_SZ>>>(out, sw2, ew2);
    gemm2_k<<<dim3(DM / 128, CAP / 128, NSEG), 256, SMEM_SZ>>>(out);
}

// round 16
// speedup vs baseline: 1.1057x; 1.1057x over previous
#include <cuda_runtime.h>
#include <cuda_fp16.h>
#include <math.h>
#include <stdint.h>

#define TT   4096
#define DM   1024
#define HH   4096
#define NE   8
#define NSEG 9
#define CAP  4096

// smem: per stage A(128x144B) + B(128x144B); 3 stages; 2 CTAs/SM
#define A_TILE_B 18432
#define B_TILE_B 18432
#define STAGE_B  36864
#define SMEM_SZ  110592

// fused aux kernel block ranges
#define WCVT_BLKS  73728
#define ZERO_BLKS  4096
#define GATE_BLKS  512

// ---------------- scratch (__device__ globals; allocation-free rule) -------
__device__ int   g_cnt[NSEG];
__device__ int   g_rowmap[NE * CAP];
__device__ float g_sgate[NE * CAP];

__device__ __align__(16) __half g_x [(size_t)NSEG * CAP * DM];
__device__ __align__(16) __half g_w1[(size_t)NSEG * HH * DM];
__device__ __align__(16) __half g_w2[(size_t)NSEG * DM * HH];
__device__ __align__(16) __half g_h [(size_t)NSEG * CAP * HH];

// ---------------- helpers ---------------------------------------------------
__device__ __forceinline__ uint32_t s2u(const void* p) {
    uint32_t a;
    asm("{ .reg .u64 t; cvta.to.shared.u64 t, %1; cvt.u32.u64 %0, t; }" : "=r"(a) : "l"(p));
    return a;
}
__device__ __forceinline__ void cpasync16(uint32_t dst, const void* src) {
    asm volatile("cp.async.cg.shared.global [%0], [%1], 16;" :: "r"(dst), "l"(src) : "memory");
}
__device__ __forceinline__ void cp_commit() { asm volatile("cp.async.commit_group;" ::: "memory"); }
template <int N> __device__ __forceinline__ void cp_wait() {
    asm volatile("cp.async.wait_group %0;" :: "n"(N) : "memory");
}
__device__ __forceinline__ void ldsm4(uint32_t* r, uint32_t a) {
    asm volatile("ldmatrix.sync.aligned.m8n8.x4.shared.b16 {%0,%1,%2,%3}, [%4];"
                 : "=r"(r[0]), "=r"(r[1]), "=r"(r[2]), "=r"(r[3]) : "r"(a));
}
__device__ __forceinline__ void ldsm2(uint32_t* r, uint32_t a) {
    asm volatile("ldmatrix.sync.aligned.m8n8.x2.shared.b16 {%0,%1}, [%2];"
                 : "=r"(r[0]), "=r"(r[1]) : "r"(a));
}
__device__ __forceinline__ void mma16816(float* c, const uint32_t* a, const uint32_t* b) {
    asm volatile("mma.sync.aligned.m16n8k16.row.col.f32.f16.f16.f32 "
                 "{%0,%1,%2,%3}, {%4,%5,%6,%7}, {%8,%9}, {%0,%1,%2,%3};"
                 : "+f"(c[0]), "+f"(c[1]), "+f"(c[2]), "+f"(c[3])
                 : "r"(a[0]), "r"(a[1]), "r"(a[2]), "r"(a[3]), "r"(b[0]), "r"(b[1]));
}
// silu via hardware tanh: x * (0.5 + 0.5*tanh(x/2)) — 1 MUFU instead of 2
__device__ __forceinline__ float silu_f(float v) {
    float t;
    asm("tanh.approx.f32 %0, %1;" : "=f"(t) : "f"(0.5f * v));
    return v * fmaf(0.5f, t, 0.5f);
}
// vectorized global reduction: one REDG for 4 floats (PTX 8.1+, sm_90+)
__device__ __forceinline__ void red_add_v4(float* addr, float a, float b, float c, float d) {
    asm volatile("red.global.add.v4.f32 [%0], {%1, %2, %3, %4};"
                 :: "l"(addr), "f"(a), "f"(b), "f"(c), "f"(d) : "memory");
}

// ---------------- reset ------------------------------------------------------
__global__ void reset_k() {
    int i = threadIdx.x;
    if (i < NE) g_cnt[i] = 0;
    if (i == NE) g_cnt[NE] = TT;
}

// ---------------- fused aux: wcvt | zero | gate ------------------------------
__global__ void aux_k(const float* __restrict__ x,  const float* __restrict__ gw,
                      const float* __restrict__ sw1, const float* __restrict__ sw2,
                      const float* __restrict__ ew1, const float* __restrict__ ew2,
                      float* __restrict__ out) {
    int bid = blockIdx.x;
    if (bid < WCVT_BLKS) {
        // ---- weight convert fp32 -> fp16 ----
        int wsel = bid / 36864;
        int rem  = bid % 36864;
        int seg  = rem / 4096;
        int blk  = rem % 4096;
        size_t segoff = (size_t)seg * HH * DM;
        const float* src;
        __half* dst;
        if (wsel == 0) { src = (seg == NE) ? sw1 : (ew1 + segoff); dst = g_w1 + segoff; }
        else           { src = (seg == NE) ? sw2 : (ew2 + segoff); dst = g_w2 + segoff; }
        size_t i4 = (size_t)blk * 256 + threadIdx.x;
        float4 v = ((const float4*)src)[i4];
        __half2* p = (__half2*)(dst + i4 * 4);
        p[0] = __floats2half2_rn(v.x, v.y);
        p[1] = __floats2half2_rn(v.z, v.w);
        return;
    }
    bid -= WCVT_BLKS;
    if (bid < ZERO_BLKS) {
        // ---- zero output ----
        size_t i = (size_t)bid * 256 + threadIdx.x;
        ((float4*)out)[i] = make_float4(0.f, 0.f, 0.f, 0.f);
        return;
    }
    bid -= ZERO_BLKS;
    {
        // ---- gating: one warp per token ----
        int gtid = bid * 256 + threadIdx.x;
        int t = gtid >> 5, lane = gtid & 31;
        const float* xr = x + (size_t)t * DM;
        float acc[NE];
#pragma unroll
        for (int e = 0; e < NE; e++) acc[e] = 0.f;
        for (int k = lane; k < DM; k += 32) {
            float xv = xr[k];
#pragma unroll
            for (int e = 0; e < NE; e++) acc[e] += xv * gw[e * DM + k];
        }
#pragma unroll
        for (int e = 0; e < NE; e++) {
#pragma unroll
            for (int o = 16; o > 0; o >>= 1) acc[e] += __shfl_xor_sync(0xffffffffu, acc[e], o);
        }
        if (lane == 0) {
            int i0 = 0; float v0 = acc[0];
#pragma unroll
            for (int e = 1; e < NE; e++) if (acc[e] > v0) { v0 = acc[e]; i0 = e; }
            int i1 = -1; float v1 = -1e30f;
#pragma unroll
            for (int e = 0; e < NE; e++) if (e != i0 && acc[e] > v1) { v1 = acc[e]; i1 = e; }
            float ex = expf(v1 - v0);
            float g0 = 1.f / (1.f + ex);
            float g1 = ex / (1.f + ex);
            int p0 = atomicAdd(&g_cnt[i0], 1);
            g_rowmap[i0 * CAP + p0] = t; g_sgate[i0 * CAP + p0] = g0;
            int p1 = atomicAdd(&g_cnt[i1], 1);
            g_rowmap[i1 * CAP + p1] = t; g_sgate[i1 * CAP + p1] = g1;
        }
    }
}

// ---------------- gather + convert activations per segment -------------------
__global__ void gather_k(const float* __restrict__ x) {
    int seg = blockIdx.y, slot = blockIdx.x;
    int cnt = g_cnt[seg];
    int pad = (cnt + 127) & ~127;
    if (slot >= pad) return;
    size_t drow = ((size_t)seg * CAP + slot) * DM;
    int i = threadIdx.x;
    float4 v = make_float4(0.f, 0.f, 0.f, 0.f);
    if (slot < cnt) {
        int tok = (seg == NE) ? slot : g_rowmap[seg * CAP + slot];
        v = ((const float4*)(x + (size_t)tok * DM))[i];
    }
    __half2* p = (__half2*)(g_x + drow + (size_t)i * 4);
    p[0] = __floats2half2_rn(v.x, v.y);
    p[1] = __floats2half2_rn(v.z, v.w);
}

// ---------------- grouped GEMM, 128x128 CTA tile, 8 warps 64x32, occ 2 -------
// 256 threads, 2x4 warp grid -> 16 warps/SM at occupancy 2
// PHASE 1: h = silu(x @ W1^T), K=1024 -> g_h (fp16)
// PHASE 2: out[tok] += gate * (h @ W2^T), K=4096 (fused combine, red.v4)
template <int PHASE>
__global__ __launch_bounds__(256, 2) void gemm_k(float* __restrict__ out) {
    constexpr int KLEN = (PHASE == 1) ? DM : HH;
    constexpr int NDIM = (PHASE == 1) ? HH : DM;
    constexpr int NC   = KLEN / 64;

    const int seg = blockIdx.z;
    const int cnt = g_cnt[seg];
    const int m0  = blockIdx.y * 128;
    if (m0 >= cnt) return;
    const int n0  = blockIdx.x * 128;

    extern __shared__ char smem[];
    const uint32_t sb = s2u(smem);

    const int tid  = threadIdx.x;
    const int lane = tid & 31;
    const int warp = tid >> 5;
    const int wm   = (warp & 1) * 64;    // 2 warps over M (64 each)
    const int wn   = (warp >> 1) * 32;   // 4 warps over N (32 each)

    const __half* Asrc, * Bsrc;
    if (PHASE == 1) {
        Asrc = g_x  + ((size_t)seg * CAP  + m0) * KLEN;
        Bsrc = g_w1 + ((size_t)seg * NDIM + n0) * KLEN;
    } else {
        Asrc = g_h  + ((size_t)seg * CAP  + m0) * KLEN;
        Bsrc = g_w2 + ((size_t)seg * NDIM + n0) * KLEN;
    }

    auto issue = [&](int c) {
        uint32_t base = sb + (c % 3) * STAGE_B;
#pragma unroll
        for (int it = 0; it < 4; it++) {                  // A: 128 rows x 8 chunks
            int o = tid + it * 256;                       // 0..1023
            int row = o >> 3, q = o & 7;
            cpasync16(base + row * 144 + q * 16,
                      Asrc + (size_t)row * KLEN + c * 64 + q * 8);
        }
#pragma unroll
        for (int it = 0; it < 4; it++) {                  // B: 128 rows x 8 chunks
            int o = tid + it * 256;
            int row = o >> 3, q = o & 7;
            cpasync16(base + A_TILE_B + row * 144 + q * 16,
                      Bsrc + (size_t)row * KLEN + c * 64 + q * 8);
        }
        cp_commit();
    };

    float acc[4][4][4];
#pragma unroll
    for (int mi = 0; mi < 4; mi++)
#pragma unroll
        for (int ni = 0; ni < 4; ni++)
#pragma unroll
            for (int r = 0; r < 4; r++) acc[mi][ni][r] = 0.f;

    issue(0);
    issue(1);

    for (int c = 0; c < NC; c++) {
        // pending groups here: {c, c+1} (or {c} on the last iter)
        if (c + 1 < NC) cp_wait<1>();
        else            cp_wait<0>();
        __syncthreads();                 // stage c visible; stage (c+2)%3 free
        if (c + 2 < NC) issue(c + 2);

        uint32_t Ab = sb + (c % 3) * STAGE_B;
        uint32_t Bb = Ab + A_TILE_B;

#pragma unroll
        for (int ks = 0; ks < 4; ks++) {
            const uint32_t acol = ks * 32 + (lane >> 4) * 16;
            const uint32_t bcol = ks * 32 + ((lane >> 3) & 1) * 16;
            uint32_t ah[4][4], bh[4][2];
#pragma unroll
            for (int mi = 0; mi < 4; mi++)
                ldsm4(ah[mi], Ab + (wm + mi * 16 + (lane & 15)) * 144 + acol);
#pragma unroll
            for (int ni = 0; ni < 4; ni++)
                ldsm2(bh[ni], Bb + (wn + ni * 8 + (lane & 7)) * 144 + bcol);
#pragma unroll
            for (int mi = 0; mi < 4; mi++)
#pragma unroll
                for (int ni = 0; ni < 4; ni++) mma16816(acc[mi][ni], ah[mi], bh[ni]);
        }
    }
    __syncthreads();                     // protect smem before epilogue reuse

    // ---- epilogue: regs -> smem (f32, stride 132) -> gmem ----
    float* SF = (float*)smem;
    int*   RI = (int*)(smem + 128 * 132 * 4);             // 67584
    float* GV = (float*)(smem + 128 * 132 * 4 + 512);

#pragma unroll
    for (int mi = 0; mi < 4; mi++)
#pragma unroll
        for (int ni = 0; ni < 4; ni++)
#pragma unroll
            for (int r = 0; r < 4; r++) {
                int row = wm + mi * 16 + (lane >> 2) + (r >> 1) * 8;
                int col = wn + ni * 8 + (lane & 3) * 2 + (r & 1);
                float v = acc[mi][ni][r];
                if (PHASE == 1) v = silu_f(v);
                SF[row * 132 + col] = v;
            }
    if (PHASE == 2 && tid < 128) {
        int m = m0 + tid;
        if (seg == NE)      { RI[tid] = m; GV[tid] = 1.f; }
        else if (m < cnt)   { RI[tid] = g_rowmap[seg * CAP + m]; GV[tid] = g_sgate[seg * CAP + m]; }
        else                { RI[tid] = 0; GV[tid] = 0.f; }
    }
    __syncthreads();

    if (PHASE == 1) {
        for (int i = tid; i < 128 * 32; i += 256) {
            int r = i >> 5, q = i & 31;
            float4 v = *(const float4*)(SF + r * 132 + q * 4);
            size_t drow = (size_t)seg * CAP + m0 + r;
            __half2* p = (__half2*)(g_h + drow * HH + n0 + q * 4);
            p[0] = __floats2half2_rn(v.x, v.y);
            p[1] = __floats2half2_rn(v.z, v.w);
        }
    } else {
        for (int i = tid; i < 128 * 32; i += 256) {
            int r = i >> 5, q = i & 31;
            float4 v = *(const float4*)(SF + r * 132 + q * 4);
            float gv = GV[r];
            float* op = out + (size_t)RI[r] * DM + n0 + q * 4;   // 16B-aligned
            red_add_v4(op, gv * v.x, gv * v.y, gv * v.z, gv * v.w);
        }
    }
}

// ---------------------------------------------------------------------------
extern "C" void kernel_launch(void* const* d_in, const int* in_sizes, int n_in,
                              void* d_out, int out_size) {
    const float* x   = (const float*)d_in[0];
    const float* sw1 = (const float*)d_in[1];
    const float* sw2 = (const float*)d_in[2];
    const float* ew1 = (const float*)d_in[3];
    const float* ew2 = (const float*)d_in[4];
    const float* gw  = (const float*)d_in[5];
    float* out = (float*)d_out;

    cudaFuncSetAttribute(gemm_k<1>, cudaFuncAttributeMaxDynamicSharedMemorySize, SMEM_SZ);
    cudaFuncSetAttribute(gemm_k<2>, cudaFuncAttributeMaxDynamicSharedMemorySize, SMEM_SZ);

    reset_k<<<1, 32>>>();
    aux_k<<<WCVT_BLKS + ZERO_BLKS + GATE_BLKS, 256>>>(x, gw, sw1, sw2, ew1, ew2, out);
    gather_k<<<dim3(CAP, NSEG), 256>>>(x);
    gemm_k<1><<<dim3(HH / 128, CAP / 128, NSEG), 256, SMEM_SZ>>>(out);
    gemm_k<2><<<dim3(DM / 128, CAP / 128, NSEG), 256, SMEM_SZ>>>(out);
}